// round 2
// baseline (speedup 1.0000x reference)
#include <cuda_runtime.h>

typedef unsigned long long u64;

// ---------------- packed fp32x2 helpers (Blackwell FFMA2 path) ----------------
__device__ __forceinline__ u64 pack_dup(float a) {
    u64 r; asm("mov.b64 %0, {%1, %1};" : "=l"(r) : "f"(a)); return r;
}
__device__ __forceinline__ void fma2(u64& c, u64 a, u64 b) {
    asm("fma.rn.f32x2 %0, %1, %2, %0;" : "+l"(c) : "l"(a), "l"(b));
}
__device__ __forceinline__ float2 unpack2(u64 v) {
    float lo, hi; asm("mov.b64 {%0, %1}, %2;" : "=f"(lo), "=f"(hi) : "l"(v));
    return make_float2(lo, hi);
}

// ---------------- problem constants ----------------
#define NB   8          // nodes per CTA
#define MCO  9
#define AA   42
#define XW   1152
#define THREADS 512

// ---------------- shared memory layout (floats) ----------------
#define S_G    0                    // 8*42*128 = 43008
#define S_B1   43008                // 72*128   = 9216
#define S_PAN  52224                // 16*256   = 4096
#define S_TG   56320                // 378
#define S_FG   (S_TG + 378)         // 378
#define S_GB   (S_FG + 378)         // 256
#define S_BB1  (S_GB + 256)         // 128
#define S_BB2  (S_BB1 + 128)        // 128
#define S_NW   (S_BB2 + 128)        // 384
#define S_RED  (S_NW + 384)         // 16 (per-warp sumsq partials)
#define SMEM_FLOATS (S_RED + 16)    // 57988 floats = 231952 bytes

// ---------------------------------------------------------------------------
// Per-degree dense 128x128 GEMM, 16 warps: warps split 128 cols into 2 halves.
// Rows r = m*8 + i grouped by degree l. Out[row][col]=sum_k W[l][col][k]*A[row][k]
// ---------------------------------------------------------------------------
__device__ __forceinline__ void gemm_degree(const float* __restrict__ A,
                                            const float* __restrict__ W,
                                            float* __restrict__ O,
                                            const float* __restrict__ bias0,
                                            float* __restrict__ s_pan)
{
    const int tid    = threadIdx.x;
    const int colgrp = (tid & 31) + ((tid >> 8) << 5);  // 0..63, covers cols 2cg,2cg+1
    const int rg     = (tid >> 5) & 7;                  // row group 0..7
    const int pcol   = tid & 127;                       // panel staging col
    const int pkq    = tid >> 7;                        // 0..3, k quartet

    const float4* wg = (const float4*)W;
    float4 pf = wg[pcol * 32 + pkq];    // tile (l=0, kt=0)

#pragma unroll
    for (int l = 0; l < 3; l++) {
        const int TR   = 2 * l + 1;
        const int base = l * l * 8;
        const float* Ar[5];
#pragma unroll
        for (int j = 0; j < 5; j++) {
            int jj = (j < TR) ? j : 0;
            Ar[j] = A + (base + rg + 8 * jj) * 128;
        }
        u64 acc[5];
#pragma unroll
        for (int j = 0; j < 5; j++) acc[j] = 0ull;

        for (int kt = 0; kt < 8; kt++) {
            __syncthreads();
            s_pan[(pkq * 4 + 0) * 128 + pcol] = pf.x;
            s_pan[(pkq * 4 + 1) * 128 + pcol] = pf.y;
            s_pan[(pkq * 4 + 2) * 128 + pcol] = pf.z;
            s_pan[(pkq * 4 + 3) * 128 + pcol] = pf.w;
            __syncthreads();

            {   // prefetch next tile
                int t = l * 8 + kt + 1;
                if (t < 24) {
                    int ll = t >> 3, ktt = t & 7;
                    pf = ((const float4*)(W + ll * 16384))[pcol * 32 + ktt * 4 + pkq];
                }
            }

            const int k0 = kt * 16;
            const u64* pan64 = (const u64*)s_pan;
#pragma unroll
            for (int kk = 0; kk < 16; kk += 2) {
                u64 w0 = pan64[(kk + 0) * 64 + colgrp];
                u64 w1 = pan64[(kk + 1) * 64 + colgrp];
#pragma unroll
                for (int j = 0; j < TR; j++) {
                    float2 a2 = *(const float2*)(Ar[j] + k0 + kk);
                    fma2(acc[j], pack_dup(a2.x), w0);
                    fma2(acc[j], pack_dup(a2.y), w1);
                }
            }
        }
        // epilogue
#pragma unroll
        for (int j = 0; j < TR; j++) {
            float2 r = unpack2(acc[j]);
            if (l == 0) {
                r.x += bias0[colgrp * 2 + 0];
                r.y += bias0[colgrp * 2 + 1];
            }
            *(float2*)(O + (base + rg + 8 * j) * 128 + colgrp * 2) = r;
        }
    }
}

// ---------------------------------------------------------------------------
// GEMM2 chunk: JR rows/thread (rows rbase+rg+16j), 8 cols/thread (4 z + 4 gate)
// ---------------------------------------------------------------------------
template <int JR>
__device__ __forceinline__ void gemm2_chunk(int rbase,
                                            float* __restrict__ s_g,
                                            const float4* __restrict__ wg4,
                                            float* __restrict__ s_pan,
                                            const float* __restrict__ s_gb)
{
    const int tid  = threadIdx.x;
    const int cg   = tid & 31;
    const int rg   = tid >> 5;        // 0..15
    const int pcol = tid & 255;
    const int pkh  = tid >> 8;        // 0..1

    const float* gr[JR];
#pragma unroll
    for (int j = 0; j < JR; j++) gr[j] = s_g + (rbase + rg + 16 * j) * 128;

    u64 aL0[JR], aL1[JR], aH0[JR], aH1[JR];
#pragma unroll
    for (int j = 0; j < JR; j++) { aL0[j] = 0ull; aL1[j] = 0ull; aH0[j] = 0ull; aH1[j] = 0ull; }

    float4 p0 = wg4[pcol * 32 + pkh * 2 + 0];
    float4 p1 = wg4[pcol * 32 + pkh * 2 + 1];

    for (int kt = 0; kt < 8; kt++) {
        __syncthreads();
        {
            const int pb = (pkh * 8) * 256 + pcol;
            s_pan[pb + 0 * 256] = p0.x; s_pan[pb + 1 * 256] = p0.y;
            s_pan[pb + 2 * 256] = p0.z; s_pan[pb + 3 * 256] = p0.w;
            s_pan[pb + 4 * 256] = p1.x; s_pan[pb + 5 * 256] = p1.y;
            s_pan[pb + 6 * 256] = p1.z; s_pan[pb + 7 * 256] = p1.w;
        }
        __syncthreads();

        if (kt < 7) {
            p0 = wg4[pcol * 32 + (kt + 1) * 4 + pkh * 2 + 0];
            p1 = wg4[pcol * 32 + (kt + 1) * 4 + pkh * 2 + 1];
        }

        const int k0 = kt * 16;
        const ulonglong2* pan2 = (const ulonglong2*)s_pan;
#pragma unroll
        for (int kk = 0; kk < 16; kk += 2) {
            ulonglong2 wloA = pan2[(kk + 0) * 64 + cg];
            ulonglong2 whiA = pan2[(kk + 0) * 64 + 32 + cg];
            ulonglong2 wloB = pan2[(kk + 1) * 64 + cg];
            ulonglong2 whiB = pan2[(kk + 1) * 64 + 32 + cg];
#pragma unroll
            for (int j = 0; j < JR; j++) {
                float2 a2 = *(const float2*)(gr[j] + k0 + kk);
                u64 ax = pack_dup(a2.x);
                u64 ay = pack_dup(a2.y);
                fma2(aL0[j], ax, wloA.x);
                fma2(aL1[j], ax, wloA.y);
                fma2(aH0[j], ax, whiA.x);
                fma2(aH1[j], ax, whiA.y);
                fma2(aL0[j], ay, wloB.x);
                fma2(aL1[j], ay, wloB.y);
                fma2(aH0[j], ay, whiB.x);
                fma2(aH1[j], ay, whiB.y);
            }
        }
    }

    const float gb0 = s_gb[cg * 4 + 0], gb1 = s_gb[cg * 4 + 1];
    const float gb2 = s_gb[cg * 4 + 2], gb3 = s_gb[cg * 4 + 3];
    const float hb0 = s_gb[128 + cg * 4 + 0], hb1 = s_gb[128 + cg * 4 + 1];
    const float hb2 = s_gb[128 + cg * 4 + 2], hb3 = s_gb[128 + cg * 4 + 3];

    // SwiGLU epilogue — each thread writes only rows it read itself.
#pragma unroll
    for (int j = 0; j < JR; j++) {
        float2 l01 = unpack2(aL0[j]), l23 = unpack2(aL1[j]);
        float2 h01 = unpack2(aH0[j]), h23 = unpack2(aH1[j]);
        float z0 = l01.x + gb0, z1 = l01.y + gb1, z2 = l23.x + gb2, z3 = l23.y + gb3;
        float g0 = h01.x + hb0, g1 = h01.y + hb1, g2v = h23.x + hb2, g3 = h23.y + hb3;
        float4 o4;
        o4.x = z0 * (1.f / (1.f + __expf(-z0))) * g0;
        o4.y = z1 * (1.f / (1.f + __expf(-z1))) * g1;
        o4.z = z2 * (1.f / (1.f + __expf(-z2))) * g2v;
        o4.w = z3 * (1.f / (1.f + __expf(-z3))) * g3;
        ((float4*)s_g)[(rbase + rg + 16 * j) * 32 + cg] = o4;
    }
}

extern "C" __global__ void __launch_bounds__(THREADS, 1)
eqffn_kernel(const float* __restrict__ x,
             const float* __restrict__ nwg,
             const float* __restrict__ w1g,
             const float* __restrict__ b1g,
             const float* __restrict__ gwg,
             const float* __restrict__ gbg,
             const float* __restrict__ w2g,
             const float* __restrict__ b2g,
             const float* __restrict__ tgg,
             const float* __restrict__ fgg,
             float* __restrict__ y,
             int N)
{
    extern __shared__ float sm[];
    float* s_g   = sm + S_G;
    float* s_h1  = sm + S_B1;
    float* s_pan = sm + S_PAN;
    float* s_tg  = sm + S_TG;
    float* s_fg  = sm + S_FG;
    float* s_gb  = sm + S_GB;
    float* s_bb1 = sm + S_BB1;
    float* s_bb2 = sm + S_BB2;
    float* s_nw  = sm + S_NW;
    float* s_red = sm + S_RED;

    const int tid  = threadIdx.x;
    const int lane = tid & 31;
    const int wrp  = tid >> 5;        // 0..15
    const int nodl = wrp >> 1;        // node-within-block 0..7
    const int half = wrp & 1;

    // small constants -> smem
    for (int i = tid; i < 378; i += THREADS) s_tg[i] = tgg[i];
    for (int i = tid; i < 378; i += THREADS) s_fg[i] = fgg[i];
    if (tid < 256) s_gb[tid] = gbg[tid];
    if (tid < 128) { s_bb1[tid] = b1g[tid]; s_bb2[tid] = b2g[tid]; }
    if (tid < 384) s_nw[tid] = nwg[tid];

    const int node = blockIdx.x * NB + nodl;
    const bool valid = node < N;

    // ---------- Phase 0: load x (half row per warp), sumsq, pack + RMS-norm ----------
    float v[18];
    float ss = 0.f;
    if (valid) {
        const float* xr = x + (size_t)node * XW + half * 576;
#pragma unroll
        for (int k = 0; k < 18; k++) { v[k] = xr[lane + 32 * k]; ss += v[k] * v[k]; }
    } else {
#pragma unroll
        for (int k = 0; k < 18; k++) v[k] = 0.f;
    }
#pragma unroll
    for (int o = 16; o; o >>= 1) ss += __shfl_xor_sync(0xffffffffu, ss, o);
    if (lane == 0) s_red[wrp] = ss;
    __syncthreads();   // s_red + s_nw ready
    const float sst = s_red[nodl * 2] + s_red[nodl * 2 + 1];
    const float rinv = rsqrtf(sst * (1.0f / 1152.0f) + 1e-6f);

#pragma unroll
    for (int k = 0; k < 18; k++) {
        int j = half * 576 + lane + 32 * k;
        int l, coeff, c;
        if (j < 128)      { l = 0; coeff = 0; c = j; }
        else if (j < 512) { l = 1; int q = j - 128; c = q / 3; coeff = 1 + (q - 3 * c); }
        else              { l = 2; int q = j - 512; c = q / 5; coeff = 4 + (q - 5 * c); }
        s_g[(coeff * NB + nodl) * 128 + c] = v[k] * rinv * s_nw[l * 128 + c];
    }
    __syncthreads();

    // ---------- Phase 1: GEMM1 ----------
    gemm_degree(s_g, w1g, s_h1, s_bb1, s_pan);
    __syncthreads();

    // ---------- Phase 2: to_grid  (each warp: one node, 21 grid points) ----------
    {
        float4 h1r[MCO];
#pragma unroll
        for (int m = 0; m < MCO; m++)
            h1r[m] = ((const float4*)s_h1)[(m * NB + nodl) * 32 + lane];
        const int a0 = half * 21;
        for (int a = a0; a < a0 + 21; a++) {
            float4 acc = make_float4(0.f, 0.f, 0.f, 0.f);
#pragma unroll
            for (int m = 0; m < MCO; m++) {
                float t = s_tg[a * MCO + m];
                acc.x += t * h1r[m].x; acc.y += t * h1r[m].y;
                acc.z += t * h1r[m].z; acc.w += t * h1r[m].w;
            }
            ((float4*)s_g)[(nodl * AA + a) * 32 + lane] = acc;
        }
    }
    __syncthreads();

    // ---------- Phase 3+4: GEMM2 (336x256x128) + SwiGLU ----------
    {
        const float4* wg4 = (const float4*)gwg;
        gemm2_chunk<6>(0,   s_g, wg4, s_pan, s_gb);
        gemm2_chunk<6>(96,  s_g, wg4, s_pan, s_gb);
        gemm2_chunk<6>(192, s_g, wg4, s_pan, s_gb);
        gemm2_chunk<3>(288, s_g, wg4, s_pan, s_gb);
    }
    __syncthreads();

    // ---------- Phase 5: from_grid (warp: one node, half the m's) ----------
    {
        const int m0   = half ? 5 : 0;
        const int mcnt = half ? 4 : 5;
        float4 acc[5];
#pragma unroll
        for (int m = 0; m < 5; m++) acc[m] = make_float4(0.f, 0.f, 0.f, 0.f);
        for (int a = 0; a < AA; a++) {
            float4 g4 = ((const float4*)s_g)[(nodl * AA + a) * 32 + lane];
#pragma unroll
            for (int m = 0; m < 5; m++) {
                if (m < mcnt) {
                    float f = s_fg[(m0 + m) * AA + a];
                    acc[m].x += f * g4.x; acc[m].y += f * g4.y;
                    acc[m].z += f * g4.z; acc[m].w += f * g4.w;
                }
            }
        }
#pragma unroll
        for (int m = 0; m < 5; m++)
            if (m < mcnt)
                ((float4*)s_h1)[((m0 + m) * NB + nodl) * 32 + lane] = acc[m];
    }
    __syncthreads();

    // ---------- Phase 6: GEMM3 ----------
    gemm_degree(s_h1, w2g, s_g, s_bb2, s_pan);
    __syncthreads();

    // ---------- Phase 7: unpack + store ----------
    if (valid) {
        float* yr = y + (size_t)node * XW;
#pragma unroll
        for (int k = 0; k < 18; k++) {
            int j = half * 576 + lane + 32 * k;
            int coeff, c;
            if (j < 128)      { coeff = 0; c = j; }
            else if (j < 512) { int q = j - 128; c = q / 3; coeff = 1 + (q - 3 * c); }
            else              { int q = j - 512; c = q / 5; coeff = 4 + (q - 5 * c); }
            yr[j] = s_g[(coeff * NB + nodl) * 128 + c];
        }
    }
}

extern "C" void kernel_launch(void* const* d_in, const int* in_sizes, int n_in,
                              void* d_out, int out_size)
{
    const float* x   = (const float*)d_in[0];
    const float* nw  = (const float*)d_in[1];
    const float* w1  = (const float*)d_in[2];
    const float* b1  = (const float*)d_in[3];
    const float* gw  = (const float*)d_in[4];
    const float* gb  = (const float*)d_in[5];
    const float* w2  = (const float*)d_in[6];
    const float* b2  = (const float*)d_in[7];
    const float* tg  = (const float*)d_in[8];
    const float* fg  = (const float*)d_in[9];
    float* y = (float*)d_out;

    const int N = in_sizes[0] / XW;
    const int smem_bytes = SMEM_FLOATS * 4;
    cudaFuncSetAttribute(eqffn_kernel, cudaFuncAttributeMaxDynamicSharedMemorySize, smem_bytes);
    const int grid = (N + NB - 1) / NB;
    eqffn_kernel<<<grid, THREADS, smem_bytes>>>(x, nw, w1, b1, gw, gb, w2, b2, tg, fg, y, N);
}